// round 1
// baseline (speedup 1.0000x reference)
#include <cuda_runtime.h>

#define BB 4
#define DD 256
#define NN 4096
#define MM 4096

#define TILE_N 128
#define TILE_M 128
#define KC 64
#define NKC (DD / KC)     // 4 k-chunks
#define NMT (MM / TILE_M) // 32 m-tiles
#define THREADS 256

#define SMEM_AS_FLOATS (DD * TILE_N)      // 32768 (A tile, persistent, pre-scaled by 2)
#define SMEM_BS_FLOATS (2 * KC * TILE_M)  // 16384 (B chunk, double buffered)
#define SMEM_YY_FLOATS (TILE_M)           // 128
#define SMEM_TG_FLOATS (3 * TILE_M)       // 384
#define SMEM_TOTAL_BYTES ((SMEM_AS_FLOATS + SMEM_BS_FLOATS + SMEM_YY_FLOATS + SMEM_TG_FLOATS) * 4)

// scratch: yy[b][m] = sum_d tgt_emb[b,d,m]^2
__device__ float g_yy[BB * MM];

__global__ void yy_kernel(const float* __restrict__ tgt_emb) {
    int b = blockIdx.y;
    int m = blockIdx.x * blockDim.x + threadIdx.x;
    const float* p = tgt_emb + b * DD * MM + m;
    float s = 0.f;
#pragma unroll 8
    for (int d = 0; d < DD; ++d) {
        float v = p[d * MM];
        s += v * v;
    }
    g_yy[b * MM + m] = s;
}

__device__ __forceinline__ unsigned long long pack2(float lo, float hi) {
    unsigned long long r;
    asm("mov.b64 %0, {%1, %2};" : "=l"(r)
        : "r"(__float_as_uint(lo)), "r"(__float_as_uint(hi)));
    return r;
}

__device__ __forceinline__ void unpack2(unsigned long long v, float& lo, float& hi) {
    unsigned a, b;
    asm("mov.b64 {%0, %1}, %2;" : "=r"(a), "=r"(b) : "l"(v));
    lo = __uint_as_float(a);
    hi = __uint_as_float(b);
}

// packed dual-FMA: d.lo = a.lo*b.lo + c.lo ; d.hi = a.hi*b.hi + c.hi
#define FMA2(d, a, b, c) \
    asm("fma.rn.f32x2 %0, %1, %2, %3;" : "=l"(d) : "l"(a), "l"(b), "l"(c))

__global__ void __launch_bounds__(THREADS, 1)
corr_kernel(const float* __restrict__ src_emb,
            const float* __restrict__ tgt_emb,
            const float* __restrict__ tgt,
            float* __restrict__ out) {
    extern __shared__ float smem[];
    float* As   = smem;                      // [DD][TILE_N], holds 2*src_emb
    float* Bs   = As + SMEM_AS_FLOATS;       // [2][KC][TILE_M]
    float* yy_s = Bs + SMEM_BS_FLOATS;       // [TILE_M]
    float* tg_s = yy_s + SMEM_YY_FLOATS;     // [3][TILE_M]

    const int tid = threadIdx.x;
    const int tx  = tid & 15;   // m direction (16 lanes, columns interleaved stride 16)
    const int ty  = tid >> 4;   // n direction (16 groups of 8 adjacent rows)
    const int b   = blockIdx.y;
    const int n0  = blockIdx.x * TILE_N;

    // ---- Load persistent A tile: As[d][n] = 2 * src_emb[b][d][n0+n] ----
    {
        const float4* g = (const float4*)(src_emb + b * DD * NN);
#pragma unroll
        for (int i = 0; i < (DD * TILE_N / 4) / THREADS; ++i) {
            int e = tid + i * THREADS;
            int f = e * 4;
            int d = f / TILE_N;
            int c = f % TILE_N;
            float4 v = g[(d * NN + n0 + c) >> 2];
            v.x *= 2.f; v.y *= 2.f; v.z *= 2.f; v.w *= 2.f;
            *(float4*)(As + d * TILE_N + c) = v;
        }
    }

    // per-row online-softmax state (rows n0 + ty*8 + r)
    float rmax[8], rsum[8], o0[8], o1[8], o2[8];
#pragma unroll
    for (int r = 0; r < 8; ++r) {
        rmax[r] = -1e30f; rsum[r] = 0.f;
        o0[r] = 0.f; o1[r] = 0.f; o2[r] = 0.f;
    }

    const float4* gB = (const float4*)(tgt_emb + b * DD * MM);

    for (int mt = 0; mt < NMT; ++mt) {
        const int m0 = mt * TILE_M;
        __syncthreads();  // previous tile's smem readers done

        // yy + tgt values for this m tile (512 floats)
        for (int e = tid; e < 4 * TILE_M; e += THREADS) {
            if (e < TILE_M) {
                yy_s[e] = g_yy[b * MM + m0 + e];
            } else {
                int q = e - TILE_M;
                int c = q / TILE_M;
                int mm = q % TILE_M;
                tg_s[c * TILE_M + mm] = tgt[b * 3 * MM + c * MM + m0 + mm];
            }
        }
        // B chunk 0
#pragma unroll
        for (int i = 0; i < 8; ++i) {
            int e = tid + i * THREADS;
            int f = e * 4;
            int k = f / TILE_M;
            int c = f % TILE_M;
            *(float4*)(Bs + k * TILE_M + c) = gB[(k * MM + m0 + c) >> 2];
        }
        __syncthreads();

        unsigned long long acc[4][8];
#pragma unroll
        for (int p = 0; p < 4; ++p)
#pragma unroll
            for (int jj = 0; jj < 8; ++jj) acc[p][jj] = 0ull;

        int cur = 0;
        for (int kc = 0; kc < NKC; ++kc) {
            // prefetch next chunk into registers
            float4 pf[8];
            if (kc + 1 < NKC) {
#pragma unroll
                for (int i = 0; i < 8; ++i) {
                    int e = tid + i * THREADS;
                    int f = e * 4;
                    int k = f / TILE_M;
                    int c = f % TILE_M;
                    pf[i] = gB[(((kc + 1) * KC + k) * MM + m0 + c) >> 2];
                }
            }
            // main register GEMM on this chunk
            const float* arow = As + (kc * KC) * TILE_N + ty * 8;
            const float* brow = Bs + cur * (KC * TILE_M) + tx;
#pragma unroll 8
            for (int k = 0; k < KC; ++k) {
                unsigned long long a2[4];
#pragma unroll
                for (int p = 0; p < 4; ++p)
                    a2[p] = *(const unsigned long long*)(arow + 2 * p);
                unsigned long long b2[8];
#pragma unroll
                for (int jj = 0; jj < 8; ++jj) {
                    float bv = brow[16 * jj];
                    b2[jj] = pack2(bv, bv);
                }
#pragma unroll
                for (int p = 0; p < 4; ++p)
#pragma unroll
                    for (int jj = 0; jj < 8; ++jj)
                        FMA2(acc[p][jj], a2[p], b2[jj], acc[p][jj]);
                arow += TILE_N;
                brow += TILE_M;
            }
            if (kc + 1 < NKC) {
                __syncthreads();
#pragma unroll
                for (int i = 0; i < 8; ++i) {
                    int e = tid + i * THREADS;
                    int f = e * 4;
                    int k = f / TILE_M;
                    int c = f % TILE_M;
                    *(float4*)(Bs + (cur ^ 1) * (KC * TILE_M) + k * TILE_M + c) = pf[i];
                }
                __syncthreads();
                cur ^= 1;
            }
        }

        // ---- epilogue: logits = acc - yy ; online softmax over m ----
        float yyv[8], tv0[8], tv1[8], tv2[8];
#pragma unroll
        for (int jj = 0; jj < 8; ++jj) {
            int mcol = tx + 16 * jj;
            yyv[jj] = yy_s[mcol];
            tv0[jj] = tg_s[mcol];
            tv1[jj] = tg_s[TILE_M + mcol];
            tv2[jj] = tg_s[2 * TILE_M + mcol];
        }

        auto do_row = [&](float (&lg)[8], int r) {
            float tmax = lg[0];
#pragma unroll
            for (int jj = 1; jj < 8; ++jj) tmax = fmaxf(tmax, lg[jj]);
#pragma unroll
            for (int off = 8; off >= 1; off >>= 1)
                tmax = fmaxf(tmax, __shfl_xor_sync(0xffffffffu, tmax, off, 16));
            float nm = fmaxf(rmax[r], tmax);
            float corr = __expf(rmax[r] - nm);
            rmax[r] = nm;
            float ls = 0.f, a0 = 0.f, a1 = 0.f, a2 = 0.f;
#pragma unroll
            for (int jj = 0; jj < 8; ++jj) {
                float pj = __expf(lg[jj] - nm);
                ls += pj;
                a0 += pj * tv0[jj];
                a1 += pj * tv1[jj];
                a2 += pj * tv2[jj];
            }
#pragma unroll
            for (int off = 8; off >= 1; off >>= 1)
                ls += __shfl_xor_sync(0xffffffffu, ls, off, 16);
            rsum[r] = rsum[r] * corr + ls;
            o0[r] = o0[r] * corr + a0;
            o1[r] = o1[r] * corr + a1;
            o2[r] = o2[r] * corr + a2;
        };

#pragma unroll
        for (int p = 0; p < 4; ++p) {
            float lgA[8], lgB[8];
#pragma unroll
            for (int jj = 0; jj < 8; ++jj) {
                float lo, hi;
                unpack2(acc[p][jj], lo, hi);
                lgA[jj] = lo - yyv[jj];
                lgB[jj] = hi - yyv[jj];
            }
            do_row(lgA, 2 * p);
            do_row(lgB, 2 * p + 1);
        }
    }

    // ---- final: reduce partial o across the 16 m-lanes, write out ----
#pragma unroll
    for (int r = 0; r < 8; ++r) {
        float v0 = o0[r], v1 = o1[r], v2 = o2[r];
#pragma unroll
        for (int off = 8; off >= 1; off >>= 1) {
            v0 += __shfl_xor_sync(0xffffffffu, v0, off, 16);
            v1 += __shfl_xor_sync(0xffffffffu, v1, off, 16);
            v2 += __shfl_xor_sync(0xffffffffu, v2, off, 16);
        }
        if (tx == 0) {
            int n = n0 + ty * 8 + r;
            float inv = 1.f / rsum[r];
            out[b * 3 * NN + n]          = v0 * inv;
            out[b * 3 * NN + NN + n]     = v1 * inv;
            out[b * 3 * NN + 2 * NN + n] = v2 * inv;
        }
    }
}

extern "C" void kernel_launch(void* const* d_in, const int* in_sizes, int n_in,
                              void* d_out, int out_size) {
    // inputs per metadata: [0]=src (unused), [1]=tgt, [2]=src_emb, [3]=tgt_emb
    const float* tgt     = (const float*)d_in[1];
    const float* src_emb = (const float*)d_in[2];
    const float* tgt_emb = (const float*)d_in[3];
    float* out = (float*)d_out;

    cudaFuncSetAttribute(corr_kernel,
                         cudaFuncAttributeMaxDynamicSharedMemorySize,
                         SMEM_TOTAL_BYTES);

    yy_kernel<<<dim3(MM / THREADS, BB), THREADS>>>(tgt_emb);
    corr_kernel<<<dim3(NN / TILE_N, BB), THREADS, SMEM_TOTAL_BYTES>>>(
        src_emb, tgt_emb, tgt, out);
}